// round 1
// baseline (speedup 1.0000x reference)
#include <cuda_runtime.h>

// ---------------------------------------------------------------------------
// StateUpdate: scatter-mean(bonds)->[G,128], scatter-mean(sites)->[G,128],
// concat with states -> [G,384], then 3x (Linear + ReLU).
//
// Strategy: counting-sort row indices by graph id (histogram -> scan ->
// scatter), then one CTA per graph gathers its rows coalesced (512B per row)
// and reduces in registers. No float atomics anywhere. MLP via fp32 SIMT
// tiled GEMMs (BM=BN=64, BK=16, 4x4 register tile, float4 smem reads).
// ---------------------------------------------------------------------------

namespace {
constexpr int G    = 8192;
constexpr int F    = 128;      // feature length of sites/bonds/states
constexpr int NBND = 2000000;
constexpr int NSIT = 500000;
constexpr int VW   = 384;      // concat width
}

// Scratch (static device globals: allocation-free per harness rules)
__device__ int   d_cnt[2][G];          // [0]=bonds, [1]=sites
__device__ int   d_off[2][G + 1];
__device__ int   d_cur[2][G];
__device__ int   d_bond_sorted[NBND];
__device__ int   d_site_sorted[NSIT];
__device__ float d_V [(long)G * VW];   // pooled+concat
__device__ float d_H1[(long)G * 256];
__device__ float d_H2[(long)G * 256];

// ---------------------------------------------------------------------------
__global__ void zero_counts_kernel() {
    int i = blockIdx.x * blockDim.x + threadIdx.x;
    if (i < G) { d_cnt[0][i] = 0; d_cnt[1][i] = 0; }
}

__global__ void hist_kernel(const int* __restrict__ idx, int n, int which) {
    int i = blockIdx.x * blockDim.x + threadIdx.x;
    if (i < n) atomicAdd(&d_cnt[which][idx[i]], 1);
}

// Exclusive scan over 8192 counters; single CTA of 256 threads, 32 per thread.
__global__ void scan_kernel(int which) {
    __shared__ int part[256];
    const int* cnt = d_cnt[which];
    int* off = d_off[which];
    int* cur = d_cur[which];
    int t = threadIdx.x;
    int base = t * 32;
    int local[32];
    int s = 0;
#pragma unroll
    for (int i = 0; i < 32; i++) { local[i] = s; s += cnt[base + i]; }
    part[t] = s;
    __syncthreads();
    if (t == 0) {
        int acc = 0;
        for (int i = 0; i < 256; i++) { int v = part[i]; part[i] = acc; acc += v; }
    }
    __syncthreads();
    int p = part[t];
#pragma unroll
    for (int i = 0; i < 32; i++) {
        int o = p + local[i];
        off[base + i] = o;
        cur[base + i] = o;
    }
    if (t == 255) off[G] = p + s;
}

__global__ void scatter_kernel(const int* __restrict__ idx, int n, int which) {
    int i = blockIdx.x * blockDim.x + threadIdx.x;
    if (i < n) {
        int g = idx[i];
        int p = atomicAdd(&d_cur[which][g], 1);
        if (which == 0) d_bond_sorted[p] = i;
        else            d_site_sorted[p] = i;
    }
}

// ---------------------------------------------------------------------------
// Pool: one CTA (128 threads) per graph. Thread t owns feature t.
// Rows gathered via sorted index list staged through smem; 4-row unroll keeps
// 4 independent LDGs in flight per thread (MLP >= 4).
__device__ __forceinline__ float seg_mean(const float* __restrict__ data,
                                          const int* __restrict__ sorted,
                                          int s, int e, int tid, int* sidx) {
    float acc = 0.f;
    for (int base = s; base < e; base += 128) {
        int m = e - base; if (m > 128) m = 128;
        __syncthreads();
        if (tid < m) sidx[tid] = sorted[base + tid];
        __syncthreads();
        int j = 0;
        for (; j + 4 <= m; j += 4) {
            float v0 = data[(long)sidx[j + 0] * F + tid];
            float v1 = data[(long)sidx[j + 1] * F + tid];
            float v2 = data[(long)sidx[j + 2] * F + tid];
            float v3 = data[(long)sidx[j + 3] * F + tid];
            acc += (v0 + v1) + (v2 + v3);
        }
        for (; j < m; j++) acc += data[(long)sidx[j] * F + tid];
    }
    int c = e - s;
    return acc / (float)(c > 0 ? c : 1);
}

__global__ __launch_bounds__(128) void pool_kernel(
    const float* __restrict__ bonds,
    const float* __restrict__ sites,
    const float* __restrict__ states) {
    __shared__ int sidx[128];
    int g = blockIdx.x;
    int tid = threadIdx.x;
    float mb = seg_mean(bonds, d_bond_sorted, d_off[0][g], d_off[0][g + 1], tid, sidx);
    float ms = seg_mean(sites, d_site_sorted, d_off[1][g], d_off[1][g + 1], tid, sidx);
    long vb = (long)g * VW;
    d_V[vb + tid]        = mb;
    d_V[vb + 128 + tid]  = ms;
    d_V[vb + 256 + tid]  = states[(long)g * F + tid];
}

// ---------------------------------------------------------------------------
// GEMM: C[M,N] = relu(A[M,K] @ W[N,K]^T + bias), all row-major fp32.
// BM=BN=64, BK=16, 256 threads (16x16), 4x4 per-thread tile.
__global__ __launch_bounds__(256) void gemm_bias_relu(
    const float* __restrict__ A, const float* __restrict__ W,
    const float* __restrict__ bias, float* __restrict__ C,
    int M, int N, int K) {
    __shared__ __align__(16) float As[16][68];  // [k][m], padded
    __shared__ __align__(16) float Bs[16][68];  // [k][n], padded

    int tid = threadIdx.x;
    int tx = tid % 16, ty = tid / 16;
    int m0 = blockIdx.y * 64, n0 = blockIdx.x * 64;
    int lr = tid / 4;            // 0..63
    int lk = (tid % 4) * 4;      // 0,4,8,12

    float acc[4][4] = {};

    for (int k0 = 0; k0 < K; k0 += 16) {
        float4 a = *(const float4*)&A[(long)(m0 + lr) * K + k0 + lk];
        float4 b = *(const float4*)&W[(long)(n0 + lr) * K + k0 + lk];
        __syncthreads();
        As[lk + 0][lr] = a.x; As[lk + 1][lr] = a.y;
        As[lk + 2][lr] = a.z; As[lk + 3][lr] = a.w;
        Bs[lk + 0][lr] = b.x; Bs[lk + 1][lr] = b.y;
        Bs[lk + 2][lr] = b.z; Bs[lk + 3][lr] = b.w;
        __syncthreads();
#pragma unroll
        for (int k = 0; k < 16; k++) {
            float4 av = *(const float4*)&As[k][ty * 4];
            float4 bv = *(const float4*)&Bs[k][tx * 4];
            float aa[4] = {av.x, av.y, av.z, av.w};
            float bb[4] = {bv.x, bv.y, bv.z, bv.w};
#pragma unroll
            for (int i = 0; i < 4; i++)
#pragma unroll
                for (int j = 0; j < 4; j++)
                    acc[i][j] += aa[i] * bb[j];
        }
    }

#pragma unroll
    for (int i = 0; i < 4; i++) {
        int m = m0 + ty * 4 + i;
        float4 o;
        float* po = &o.x;
#pragma unroll
        for (int j = 0; j < 4; j++) {
            int n = n0 + tx * 4 + j;
            float v = acc[i][j] + bias[n];
            po[j] = v > 0.f ? v : 0.f;
        }
        *(float4*)&C[(long)m * N + n0 + tx * 4] = o;
    }
}

// ---------------------------------------------------------------------------
extern "C" void kernel_launch(void* const* d_in, const int* in_sizes, int n_in,
                              void* d_out, int out_size) {
    const float* sites  = (const float*)d_in[0];
    const float* bonds  = (const float*)d_in[1];
    const float* states = (const float*)d_in[2];
    const int*   g2s    = (const int*)d_in[3];
    const int*   g2b    = (const int*)d_in[4];
    const float* W1 = (const float*)d_in[5];
    const float* b1 = (const float*)d_in[6];
    const float* W2 = (const float*)d_in[7];
    const float* b2 = (const float*)d_in[8];
    const float* W3 = (const float*)d_in[9];
    const float* b3 = (const float*)d_in[10];
    float* out = (float*)d_out;

    int ns = in_sizes[3];   // 500000
    int nb = in_sizes[4];   // 2000000

    void *pV, *pH1, *pH2;
    cudaGetSymbolAddress(&pV,  d_V);
    cudaGetSymbolAddress(&pH1, d_H1);
    cudaGetSymbolAddress(&pH2, d_H2);

    // 1) counting sort of row ids by graph
    zero_counts_kernel<<<(G + 255) / 256, 256>>>();
    hist_kernel<<<(nb + 255) / 256, 256>>>(g2b, nb, 0);
    hist_kernel<<<(ns + 255) / 256, 256>>>(g2s, ns, 1);
    scan_kernel<<<1, 256>>>(0);
    scan_kernel<<<1, 256>>>(1);
    scatter_kernel<<<(nb + 255) / 256, 256>>>(g2b, nb, 0);
    scatter_kernel<<<(ns + 255) / 256, 256>>>(g2s, ns, 1);

    // 2) pooled gather + concat -> d_V [G,384]
    pool_kernel<<<G, 128>>>(bonds, sites, states);

    // 3) MLP
    gemm_bias_relu<<<dim3(256 / 64, G / 64), 256>>>((const float*)pV,  W1, b1, (float*)pH1, G, 256, 384);
    gemm_bias_relu<<<dim3(256 / 64, G / 64), 256>>>((const float*)pH1, W2, b2, (float*)pH2, G, 256, 256);
    gemm_bias_relu<<<dim3(128 / 64, G / 64), 256>>>((const float*)pH2, W3, b3, out,         G, 128, 256);
}

// round 2
// speedup vs baseline: 1.0844x; 1.0844x over previous
#include <cuda_runtime.h>

// ---------------------------------------------------------------------------
// StateUpdate: scatter-mean(bonds)->[G,128], scatter-mean(sites)->[G,128],
// concat with states -> [G,384], then 3x (Linear + ReLU).
//
// R2: parallel warp-shuffle scan (was serial, 2x17.7us), pool via
// warp-per-row LDG.128 with dual accumulators, GEMM 128x64 tile w/ 8x4
// per-thread register tile + gmem prefetch.
// ---------------------------------------------------------------------------

namespace {
constexpr int G    = 8192;
constexpr int F    = 128;
constexpr int NBND = 2000000;
constexpr int NSIT = 500000;
constexpr int VW   = 384;
}

__device__ int   d_cnt[2][G];
__device__ int   d_off[2][G + 1];
__device__ int   d_cur[2][G];
__device__ int   d_bond_sorted[NBND];
__device__ int   d_site_sorted[NSIT];
__device__ float d_V [(long)G * VW];
__device__ float d_H1[(long)G * 256];
__device__ float d_H2[(long)G * 256];

// ---------------------------------------------------------------------------
__global__ void zero_counts_kernel() {
    int i = blockIdx.x * blockDim.x + threadIdx.x;
    if (i < G) { d_cnt[0][i] = 0; d_cnt[1][i] = 0; }
}

__global__ void hist_kernel(const int* __restrict__ idx, int n, int which) {
    int i = blockIdx.x * blockDim.x + threadIdx.x;
    if (i < n) atomicAdd(&d_cnt[which][idx[i]], 1);
}

// Parallel exclusive scan over 8192 counters. blockIdx.x selects bonds/sites.
// 256 threads x 32 elems; warp-shuffle scan of the 256 partials.
__global__ __launch_bounds__(256) void scan_kernel() {
    __shared__ int wsum[8];
    int which = blockIdx.x;
    const int* cnt = d_cnt[which];
    int* off = d_off[which];
    int* cur = d_cur[which];
    int t = threadIdx.x, lane = t & 31, w = t >> 5;
    int base = t * 32;

    int local[32];
    int s = 0;
#pragma unroll
    for (int i = 0; i < 32; i++) { local[i] = s; s += cnt[base + i]; }

    // inclusive warp scan of per-thread sums
    int inc = s;
#pragma unroll
    for (int d = 1; d < 32; d <<= 1) {
        int v = __shfl_up_sync(0xFFFFFFFFu, inc, d);
        if (lane >= d) inc += v;
    }
    if (lane == 31) wsum[w] = inc;
    __syncthreads();
    if (w == 0) {
        int v = (lane < 8) ? wsum[lane] : 0;
        int wi = v;
#pragma unroll
        for (int d = 1; d < 8; d <<= 1) {
            int u = __shfl_up_sync(0xFFFFFFFFu, wi, d);
            if (lane >= d) wi += u;
        }
        if (lane < 8) wsum[lane] = wi - v;   // exclusive
    }
    __syncthreads();
    int thread_excl = wsum[w] + inc - s;     // exclusive prefix of this thread
#pragma unroll
    for (int i = 0; i < 32; i++) {
        int o = thread_excl + local[i];
        off[base + i] = o;
        cur[base + i] = o;
    }
    if (t == 255) off[G] = thread_excl + s;
}

__global__ void scatter_kernel(const int* __restrict__ idx, int n, int which) {
    int i = blockIdx.x * blockDim.x + threadIdx.x;
    if (i < n) {
        int g = idx[i];
        int p = atomicAdd(&d_cur[which][g], 1);
        if (which == 0) d_bond_sorted[p] = i;
        else            d_site_sorted[p] = i;
    }
}

// ---------------------------------------------------------------------------
// Pool: one CTA (256 thr, 8 warps) per graph. Each warp loads whole rows
// (32 lanes x float4 = 512B, LDG.128). Dual accumulators keep 2 loads in
// flight per lane. Cross-warp reduce via smem at the end of each segment.
__device__ __forceinline__ void seg_mean_v4(
    const float* __restrict__ data, const int* __restrict__ sorted,
    int s, int e, int tid, int lane, int w,
    int* sidx, float* sred, float* outp) {

    float4 a0 = make_float4(0.f, 0.f, 0.f, 0.f);
    float4 a1 = make_float4(0.f, 0.f, 0.f, 0.f);

    for (int base = s; base < e; base += 256) {
        int m = e - base; if (m > 256) m = 256;
        __syncthreads();
        if (tid < m) sidx[tid] = sorted[base + tid];
        __syncthreads();
        int j = w;
        for (; j + 8 < m; j += 16) {
            const float4* r0 = (const float4*)(data + (long)sidx[j]     * F);
            const float4* r1 = (const float4*)(data + (long)sidx[j + 8] * F);
            float4 v0 = r0[lane];
            float4 v1 = r1[lane];
            a0.x += v0.x; a0.y += v0.y; a0.z += v0.z; a0.w += v0.w;
            a1.x += v1.x; a1.y += v1.y; a1.z += v1.z; a1.w += v1.w;
        }
        if (j < m) {
            const float4* r0 = (const float4*)(data + (long)sidx[j] * F);
            float4 v0 = r0[lane];
            a0.x += v0.x; a0.y += v0.y; a0.z += v0.z; a0.w += v0.w;
        }
    }
    a0.x += a1.x; a0.y += a1.y; a0.z += a1.z; a0.w += a1.w;

    __syncthreads();
    *(float4*)&sred[w * F + lane * 4] = a0;
    __syncthreads();
    if (tid < F) {
        float sum = 0.f;
#pragma unroll
        for (int ww = 0; ww < 8; ww++) sum += sred[ww * F + tid];
        int c = e - s;
        outp[tid] = sum / (float)(c > 0 ? c : 1);
    }
}

__global__ __launch_bounds__(256) void pool_kernel(
    const float* __restrict__ bonds,
    const float* __restrict__ sites,
    const float* __restrict__ states) {
    __shared__ int   sidx[256];
    __shared__ float sred[8 * F];
    int g = blockIdx.x;
    int tid = threadIdx.x, lane = tid & 31, w = tid >> 5;
    long vb = (long)g * VW;

    seg_mean_v4(bonds, d_bond_sorted, d_off[0][g], d_off[0][g + 1],
                tid, lane, w, sidx, sred, &d_V[vb]);
    seg_mean_v4(sites, d_site_sorted, d_off[1][g], d_off[1][g + 1],
                tid, lane, w, sidx, sred, &d_V[vb + 128]);
    if (tid < F) d_V[vb + 256 + tid] = states[(long)g * F + tid];
}

// ---------------------------------------------------------------------------
// GEMM: C[M,N] = relu(A[M,K] @ W[N,K]^T + bias). BM=128, BN=64, BK=16,
// 256 threads, 8x4 per-thread tile, gmem prefetch into registers.
__global__ __launch_bounds__(256) void gemm_bias_relu(
    const float* __restrict__ A, const float* __restrict__ W,
    const float* __restrict__ bias, float* __restrict__ C,
    int M, int N, int K) {
    __shared__ __align__(16) float As[16][132];  // [k][m]
    __shared__ __align__(16) float Bs[16][68];   // [k][n]

    int tid = threadIdx.x;
    int tx = tid % 16, ty = tid / 16;
    int m0 = blockIdx.y * 128, n0 = blockIdx.x * 64;
    int lr = tid / 4;            // 0..63
    int lk = (tid % 4) * 4;      // 0,4,8,12

    const float* pa0 = &A[(long)(m0 + lr)      * K + lk];
    const float* pa1 = &A[(long)(m0 + lr + 64) * K + lk];
    const float* pw  = &W[(long)(n0 + lr)      * K + lk];

    float4 ra0 = *(const float4*)pa0;
    float4 ra1 = *(const float4*)pa1;
    float4 rb  = *(const float4*)pw;

    float acc[8][4] = {};

    for (int k0 = 0; k0 < K; k0 += 16) {
        As[lk + 0][lr] = ra0.x; As[lk + 1][lr] = ra0.y;
        As[lk + 2][lr] = ra0.z; As[lk + 3][lr] = ra0.w;
        As[lk + 0][lr + 64] = ra1.x; As[lk + 1][lr + 64] = ra1.y;
        As[lk + 2][lr + 64] = ra1.z; As[lk + 3][lr + 64] = ra1.w;
        Bs[lk + 0][lr] = rb.x; Bs[lk + 1][lr] = rb.y;
        Bs[lk + 2][lr] = rb.z; Bs[lk + 3][lr] = rb.w;
        __syncthreads();

        if (k0 + 16 < K) {
            ra0 = *(const float4*)(pa0 + k0 + 16);
            ra1 = *(const float4*)(pa1 + k0 + 16);
            rb  = *(const float4*)(pw  + k0 + 16);
        }

#pragma unroll
        for (int k = 0; k < 16; k++) {
            float4 av0 = *(const float4*)&As[k][ty * 8];
            float4 av1 = *(const float4*)&As[k][ty * 8 + 4];
            float4 bv  = *(const float4*)&Bs[k][tx * 4];
            float aa[8] = {av0.x, av0.y, av0.z, av0.w, av1.x, av1.y, av1.z, av1.w};
            float bb[4] = {bv.x, bv.y, bv.z, bv.w};
#pragma unroll
            for (int i = 0; i < 8; i++)
#pragma unroll
                for (int j = 0; j < 4; j++)
                    acc[i][j] += aa[i] * bb[j];
        }
        __syncthreads();
    }

    float4 bsv = *(const float4*)&bias[n0 + tx * 4];
    float bb4[4] = {bsv.x, bsv.y, bsv.z, bsv.w};
#pragma unroll
    for (int i = 0; i < 8; i++) {
        int m = m0 + ty * 8 + i;
        float4 o;
        float* po = &o.x;
#pragma unroll
        for (int j = 0; j < 4; j++) {
            float v = acc[i][j] + bb4[j];
            po[j] = v > 0.f ? v : 0.f;
        }
        *(float4*)&C[(long)m * N + n0 + tx * 4] = o;
    }
}

// ---------------------------------------------------------------------------
extern "C" void kernel_launch(void* const* d_in, const int* in_sizes, int n_in,
                              void* d_out, int out_size) {
    const float* sites  = (const float*)d_in[0];
    const float* bonds  = (const float*)d_in[1];
    const float* states = (const float*)d_in[2];
    const int*   g2s    = (const int*)d_in[3];
    const int*   g2b    = (const int*)d_in[4];
    const float* W1 = (const float*)d_in[5];
    const float* b1 = (const float*)d_in[6];
    const float* W2 = (const float*)d_in[7];
    const float* b2 = (const float*)d_in[8];
    const float* W3 = (const float*)d_in[9];
    const float* b3 = (const float*)d_in[10];
    float* out = (float*)d_out;

    int ns = in_sizes[3];
    int nb = in_sizes[4];

    void *pV, *pH1, *pH2;
    cudaGetSymbolAddress(&pV,  d_V);
    cudaGetSymbolAddress(&pH1, d_H1);
    cudaGetSymbolAddress(&pH2, d_H2);

    zero_counts_kernel<<<(G + 255) / 256, 256>>>();
    hist_kernel<<<(nb + 255) / 256, 256>>>(g2b, nb, 0);
    hist_kernel<<<(ns + 255) / 256, 256>>>(g2s, ns, 1);
    scan_kernel<<<2, 256>>>();
    scatter_kernel<<<(nb + 255) / 256, 256>>>(g2b, nb, 0);
    scatter_kernel<<<(ns + 255) / 256, 256>>>(g2s, ns, 1);

    pool_kernel<<<G, 256>>>(bonds, sites, states);

    gemm_bias_relu<<<dim3(256 / 64, G / 128), 256>>>((const float*)pV,  W1, b1, (float*)pH1, G, 256, 384);
    gemm_bias_relu<<<dim3(256 / 64, G / 128), 256>>>((const float*)pH1, W2, b2, (float*)pH2, G, 256, 256);
    gemm_bias_relu<<<dim3(128 / 64, G / 128), 256>>>((const float*)pH2, W3, b3, out,         G, 128, 256);
}

// round 3
// speedup vs baseline: 1.0903x; 1.0054x over previous
#include <cuda_runtime.h>

// ---------------------------------------------------------------------------
// StateUpdate: scatter-mean(bonds)->[G,128], scatter-mean(sites)->[G,128],
// concat with states -> [G,384], then 3x (Linear + ReLU).
//
// R3: GEMM via packed fma.rn.f32x2 (2 FMA/issue, ptxas won't emit it from
// C++); pool with 4 independent LDG.128 accumulators; memset for counters.
// ---------------------------------------------------------------------------

namespace {
constexpr int G    = 8192;
constexpr int F    = 128;
constexpr int NBND = 2000000;
constexpr int NSIT = 500000;
constexpr int VW   = 384;
}

__device__ int   d_cnt[2][G];
__device__ int   d_off[2][G + 1];
__device__ int   d_cur[2][G];
__device__ int   d_bond_sorted[NBND];
__device__ int   d_site_sorted[NSIT];
__device__ float d_V [(long)G * VW];
__device__ float d_H1[(long)G * 256];
__device__ float d_H2[(long)G * 256];

// ---------------------------------------------------------------------------
__global__ void hist_kernel(const int* __restrict__ idx, int n, int which) {
    int i = blockIdx.x * blockDim.x + threadIdx.x;
    if (i < n) atomicAdd(&d_cnt[which][idx[i]], 1);
}

// Parallel exclusive scan over 8192 counters. blockIdx.x selects bonds/sites.
__global__ __launch_bounds__(256) void scan_kernel() {
    __shared__ int wsum[8];
    int which = blockIdx.x;
    const int* cnt = d_cnt[which];
    int* off = d_off[which];
    int* cur = d_cur[which];
    int t = threadIdx.x, lane = t & 31, w = t >> 5;
    int base = t * 32;

    int local[32];
    int s = 0;
#pragma unroll
    for (int i = 0; i < 32; i++) { local[i] = s; s += cnt[base + i]; }

    int inc = s;
#pragma unroll
    for (int d = 1; d < 32; d <<= 1) {
        int v = __shfl_up_sync(0xFFFFFFFFu, inc, d);
        if (lane >= d) inc += v;
    }
    if (lane == 31) wsum[w] = inc;
    __syncthreads();
    if (w == 0) {
        int v = (lane < 8) ? wsum[lane] : 0;
        int wi = v;
#pragma unroll
        for (int d = 1; d < 8; d <<= 1) {
            int u = __shfl_up_sync(0xFFFFFFFFu, wi, d);
            if (lane >= d) wi += u;
        }
        if (lane < 8) wsum[lane] = wi - v;
    }
    __syncthreads();
    int thread_excl = wsum[w] + inc - s;
#pragma unroll
    for (int i = 0; i < 32; i++) {
        int o = thread_excl + local[i];
        off[base + i] = o;
        cur[base + i] = o;
    }
    if (t == 255) off[G] = thread_excl + s;
}

__global__ void scatter_kernel(const int* __restrict__ idx, int n, int which) {
    int i = blockIdx.x * blockDim.x + threadIdx.x;
    if (i < n) {
        int g = idx[i];
        int p = atomicAdd(&d_cur[which][g], 1);
        if (which == 0) d_bond_sorted[p] = i;
        else            d_site_sorted[p] = i;
    }
}

// ---------------------------------------------------------------------------
// Pool: one CTA (256 thr, 8 warps) per graph; warp-per-row LDG.128 gather,
// 4 independent accumulators (MLP_p1 = 4).
__device__ __forceinline__ void v4add(float4& a, const float4& v) {
    a.x += v.x; a.y += v.y; a.z += v.z; a.w += v.w;
}

__device__ __forceinline__ void seg_mean_v4(
    const float* __restrict__ data, const int* __restrict__ sorted,
    int s, int e, int tid, int lane, int w,
    int* sidx, float* sred, float* outp) {

    float4 a0 = make_float4(0.f,0.f,0.f,0.f), a1 = a0, a2 = a0, a3 = a0;

    for (int base = s; base < e; base += 256) {
        int m = e - base; if (m > 256) m = 256;
        __syncthreads();
        if (tid < m) sidx[tid] = sorted[base + tid];
        __syncthreads();
        int j = w;
        for (; j + 24 < m; j += 32) {
            float4 v0 = ((const float4*)(data + (long)sidx[j]      * F))[lane];
            float4 v1 = ((const float4*)(data + (long)sidx[j + 8]  * F))[lane];
            float4 v2 = ((const float4*)(data + (long)sidx[j + 16] * F))[lane];
            float4 v3 = ((const float4*)(data + (long)sidx[j + 24] * F))[lane];
            v4add(a0, v0); v4add(a1, v1); v4add(a2, v2); v4add(a3, v3);
        }
        for (; j < m; j += 8) {
            float4 v0 = ((const float4*)(data + (long)sidx[j] * F))[lane];
            v4add(a0, v0);
        }
    }
    v4add(a0, a1); v4add(a2, a3); v4add(a0, a2);

    __syncthreads();
    *(float4*)&sred[w * F + lane * 4] = a0;
    __syncthreads();
    if (tid < F) {
        float sum = 0.f;
#pragma unroll
        for (int ww = 0; ww < 8; ww++) sum += sred[ww * F + tid];
        int c = e - s;
        outp[tid] = sum / (float)(c > 0 ? c : 1);
    }
}

__global__ __launch_bounds__(256) void pool_kernel(
    const float* __restrict__ bonds,
    const float* __restrict__ sites,
    const float* __restrict__ states) {
    __shared__ int   sidx[256];
    __shared__ float sred[8 * F];
    int g = blockIdx.x;
    int tid = threadIdx.x, lane = tid & 31, w = tid >> 5;
    long vb = (long)g * VW;

    seg_mean_v4(bonds, d_bond_sorted, d_off[0][g], d_off[0][g + 1],
                tid, lane, w, sidx, sred, &d_V[vb]);
    seg_mean_v4(sites, d_site_sorted, d_off[1][g], d_off[1][g + 1],
                tid, lane, w, sidx, sred, &d_V[vb + 128]);
    if (tid < F) d_V[vb + 256 + tid] = states[(long)g * F + tid];
}

// ---------------------------------------------------------------------------
// Packed fp32x2 helpers
__device__ __forceinline__ unsigned long long f32x2_dup(float a) {
    unsigned long long r;
    asm("mov.b64 %0, {%1, %1};" : "=l"(r) : "f"(a));
    return r;
}
__device__ __forceinline__ void ffma2(unsigned long long& d,
                                      unsigned long long a,
                                      unsigned long long b) {
    asm("fma.rn.f32x2 %0, %1, %2, %0;" : "+l"(d) : "l"(a), "l"(b));
}
__device__ __forceinline__ float2 f32x2_unpack(unsigned long long v) {
    float lo, hi;
    asm("mov.b64 {%0, %1}, %2;" : "=f"(lo), "=f"(hi) : "l"(v));
    return make_float2(lo, hi);
}

// GEMM: C[M,N] = relu(A[M,K] @ W[N,K]^T + bias). BM=128, BN template,
// BK=16, 256 threads, per-thread 8m x (BN/16)n with f32x2 accumulators.
template <int BN>
__global__ __launch_bounds__(256) void gemm_f32x2(
    const float* __restrict__ A, const float* __restrict__ W,
    const float* __restrict__ bias, float* __restrict__ C,
    int M, int N, int K) {
    constexpr int TN = BN / 16;   // n-floats per thread (8 or 4)
    constexpr int P  = TN / 2;    // f32x2 pairs per thread (4 or 2)
    __shared__ __align__(16) float As[16][132];
    __shared__ __align__(16) float Bs[16][BN + 4];

    int tid = threadIdx.x;
    int tx = tid % 16, ty = tid / 16;
    int m0 = blockIdx.y * 128, n0 = blockIdx.x * BN;
    int lr = tid / 4;
    int lk = (tid % 4) * 4;

    const float* pa0 = &A[(long)(m0 + lr)      * K + lk];
    const float* pa1 = &A[(long)(m0 + lr + 64) * K + lk];
    // B tile: BN rows; 256 threads place 64 rows per wave.
    const float* pw0 = &W[(long)(n0 + (lr % BN))              * K + lk];
    const float* pw1 = (BN > 64) ? &W[(long)(n0 + lr + 64) * K + lk] : pw0;

    float4 ra0 = *(const float4*)pa0;
    float4 ra1 = *(const float4*)pa1;
    float4 rb0 = *(const float4*)pw0;
    float4 rb1 = (BN > 64) ? *(const float4*)pw1 : ra0;

    unsigned long long acc[8][P];
#pragma unroll
    for (int i = 0; i < 8; i++)
#pragma unroll
        for (int j = 0; j < P; j++) acc[i][j] = 0ull;

    for (int k0 = 0; k0 < K; k0 += 16) {
        As[lk + 0][lr] = ra0.x; As[lk + 1][lr] = ra0.y;
        As[lk + 2][lr] = ra0.z; As[lk + 3][lr] = ra0.w;
        As[lk + 0][lr + 64] = ra1.x; As[lk + 1][lr + 64] = ra1.y;
        As[lk + 2][lr + 64] = ra1.z; As[lk + 3][lr + 64] = ra1.w;
        if (BN > 64 || lr < BN) {
            int br = lr % BN;
            Bs[lk + 0][br] = rb0.x; Bs[lk + 1][br] = rb0.y;
            Bs[lk + 2][br] = rb0.z; Bs[lk + 3][br] = rb0.w;
        }
        if (BN > 64) {
            Bs[lk + 0][lr + 64] = rb1.x; Bs[lk + 1][lr + 64] = rb1.y;
            Bs[lk + 2][lr + 64] = rb1.z; Bs[lk + 3][lr + 64] = rb1.w;
        }
        __syncthreads();

        if (k0 + 16 < K) {
            ra0 = *(const float4*)(pa0 + k0 + 16);
            ra1 = *(const float4*)(pa1 + k0 + 16);
            rb0 = *(const float4*)(pw0 + k0 + 16);
            if (BN > 64) rb1 = *(const float4*)(pw1 + k0 + 16);
        }

#pragma unroll
        for (int k = 0; k < 16; k++) {
            float4 av0 = *(const float4*)&As[k][ty * 8];
            float4 av1 = *(const float4*)&As[k][ty * 8 + 4];
            float av[8] = {av0.x, av0.y, av0.z, av0.w,
                           av1.x, av1.y, av1.z, av1.w};
            unsigned long long bb[P];
            {
                ulonglong2 b0 = *(const ulonglong2*)&Bs[k][tx * TN];
                bb[0] = b0.x; bb[1] = b0.y;
                if (P == 4) {
                    ulonglong2 b1 = *(const ulonglong2*)&Bs[k][tx * TN + 4];
                    bb[2] = b1.x; bb[3] = b1.y;
                }
            }
#pragma unroll
            for (int i = 0; i < 8; i++) {
                unsigned long long ai = f32x2_dup(av[i]);
#pragma unroll
                for (int j = 0; j < P; j++) ffma2(acc[i][j], ai, bb[j]);
            }
        }
        __syncthreads();
    }

    float bs[TN];
#pragma unroll
    for (int j = 0; j < TN; j++) bs[j] = bias[n0 + tx * TN + j];

#pragma unroll
    for (int i = 0; i < 8; i++) {
        int m = m0 + ty * 8 + i;
        float o[TN];
#pragma unroll
        for (int j = 0; j < P; j++) {
            float2 v = f32x2_unpack(acc[i][j]);
            float v0 = v.x + bs[2 * j],     v1 = v.y + bs[2 * j + 1];
            o[2 * j]     = v0 > 0.f ? v0 : 0.f;
            o[2 * j + 1] = v1 > 0.f ? v1 : 0.f;
        }
#pragma unroll
        for (int j = 0; j < TN; j += 4)
            *(float4*)&C[(long)m * N + n0 + tx * TN + j] =
                make_float4(o[j], o[j + 1], o[j + 2], o[j + 3]);
    }
}

// ---------------------------------------------------------------------------
extern "C" void kernel_launch(void* const* d_in, const int* in_sizes, int n_in,
                              void* d_out, int out_size) {
    const float* sites  = (const float*)d_in[0];
    const float* bonds  = (const float*)d_in[1];
    const float* states = (const float*)d_in[2];
    const int*   g2s    = (const int*)d_in[3];
    const int*   g2b    = (const int*)d_in[4];
    const float* W1 = (const float*)d_in[5];
    const float* b1 = (const float*)d_in[6];
    const float* W2 = (const float*)d_in[7];
    const float* b2 = (const float*)d_in[8];
    const float* W3 = (const float*)d_in[9];
    const float* b3 = (const float*)d_in[10];
    float* out = (float*)d_out;

    int ns = in_sizes[3];
    int nb = in_sizes[4];

    void *pV, *pH1, *pH2, *pCnt;
    cudaGetSymbolAddress(&pV,   d_V);
    cudaGetSymbolAddress(&pH1,  d_H1);
    cudaGetSymbolAddress(&pH2,  d_H2);
    cudaGetSymbolAddress(&pCnt, d_cnt);

    cudaMemsetAsync(pCnt, 0, sizeof(int) * 2 * G);
    hist_kernel<<<(nb + 255) / 256, 256>>>(g2b, nb, 0);
    hist_kernel<<<(ns + 255) / 256, 256>>>(g2s, ns, 1);
    scan_kernel<<<2, 256>>>();
    scatter_kernel<<<(nb + 255) / 256, 256>>>(g2b, nb, 0);
    scatter_kernel<<<(ns + 255) / 256, 256>>>(g2s, ns, 1);

    pool_kernel<<<G, 256>>>(bonds, sites, states);

    gemm_f32x2<128><<<dim3(2, G / 128), 256>>>((const float*)pV,  W1, b1, (float*)pH1, G, 256, 384);
    gemm_f32x2<128><<<dim3(2, G / 128), 256>>>((const float*)pH1, W2, b2, (float*)pH2, G, 256, 256);
    gemm_f32x2<64><<<dim3(2, G / 128), 256>>>((const float*)pH2, W3, b3, out,          G, 128, 256);
}

// round 4
// speedup vs baseline: 1.2568x; 1.1527x over previous
#include <cuda_runtime.h>

// ---------------------------------------------------------------------------
// StateUpdate: scatter-mean(bonds)->[G,128], scatter-mean(sites)->[G,128],
// concat with states -> [G,384], then 3x (Linear + ReLU).
//
// R4: privatized counting sort (smem histograms + smem cursors) -> zero
// global atomics; was ~125us of ATOMG contention across hist+scatter.
// ---------------------------------------------------------------------------

namespace {
constexpr int G    = 8192;
constexpr int F    = 128;
constexpr int NBND = 2000000;
constexpr int NSIT = 500000;
constexpr int VW   = 384;
constexpr int NC   = 128;      // histogram chunks (CTAs per input)
}

__device__ int   d_hist[2][NC][G];     // per-chunk counts -> rel. offsets
__device__ int   d_tot[2][G];
__device__ int   d_off[2][G + 1];
__device__ int   d_bond_sorted[NBND];
__device__ int   d_site_sorted[NSIT];
__device__ float d_V [(long)G * VW];
__device__ float d_H1[(long)G * 256];
__device__ float d_H2[(long)G * 256];

// ---------------------------------------------------------------------------
// Pass 1: private smem histogram per CTA chunk. blockIdx.y: 0=bonds 1=sites.
__global__ __launch_bounds__(256) void hist_priv(
    const int* __restrict__ g2b, int nb,
    const int* __restrict__ g2s, int ns) {
    __shared__ int h[G];
    int which = blockIdx.y;
    const int* idx = which ? g2s : g2b;
    int n = which ? ns : nb;
    int cta = blockIdx.x;
    int tid = threadIdx.x;

    for (int j = tid; j < G; j += 256) h[j] = 0;
    __syncthreads();

    int per = (n + NC - 1) / NC;
    int s = cta * per;
    int e = s + per; if (e > n) e = n;
    for (int i = s + tid; i < e; i += 256) atomicAdd(&h[idx[i]], 1);
    __syncthreads();

    for (int j = tid; j < G; j += 256) d_hist[which][cta][j] = h[j];
}

// Pass 2: per graph, exclusive scan across the NC chunk counts (in place),
// emit totals. Coalesced across g.
__global__ __launch_bounds__(256) void col_scan() {
    int g = blockIdx.x * 256 + threadIdx.x;
    int which = blockIdx.y;
    int acc = 0;
#pragma unroll 4
    for (int c = 0; c < NC; c++) {
        int v = d_hist[which][c][g];
        d_hist[which][c][g] = acc;
        acc += v;
    }
    d_tot[which][g] = acc;
}

// Pass 3: exclusive scan over 8192 totals (warp-shuffle). blockIdx.x = which.
__global__ __launch_bounds__(256) void scan_kernel() {
    __shared__ int wsum[8];
    int which = blockIdx.x;
    const int* cnt = d_tot[which];
    int* off = d_off[which];
    int t = threadIdx.x, lane = t & 31, w = t >> 5;
    int base = t * 32;

    int local[32];
    int s = 0;
#pragma unroll
    for (int i = 0; i < 32; i++) { local[i] = s; s += cnt[base + i]; }

    int inc = s;
#pragma unroll
    for (int d = 1; d < 32; d <<= 1) {
        int v = __shfl_up_sync(0xFFFFFFFFu, inc, d);
        if (lane >= d) inc += v;
    }
    if (lane == 31) wsum[w] = inc;
    __syncthreads();
    if (w == 0) {
        int v = (lane < 8) ? wsum[lane] : 0;
        int wi = v;
#pragma unroll
        for (int d = 1; d < 8; d <<= 1) {
            int u = __shfl_up_sync(0xFFFFFFFFu, wi, d);
            if (lane >= d) wi += u;
        }
        if (lane < 8) wsum[lane] = wi - v;
    }
    __syncthreads();
    int thread_excl = wsum[w] + inc - s;
#pragma unroll
    for (int i = 0; i < 32; i++) off[base + i] = thread_excl + local[i];
    if (t == 255) off[G] = thread_excl + s;
}

// Pass 4: scatter with private smem cursors; no global atomics.
__global__ __launch_bounds__(256) void scatter_priv(
    const int* __restrict__ g2b, int nb,
    const int* __restrict__ g2s, int ns) {
    __shared__ int cur[G];
    int which = blockIdx.y;
    const int* idx = which ? g2s : g2b;
    int* outp = which ? d_site_sorted : d_bond_sorted;
    int n = which ? ns : nb;
    int cta = blockIdx.x;
    int tid = threadIdx.x;

    for (int j = tid; j < G; j += 256)
        cur[j] = d_off[which][j] + d_hist[which][cta][j];
    __syncthreads();

    int per = (n + NC - 1) / NC;
    int s = cta * per;
    int e = s + per; if (e > n) e = n;
    for (int i = s + tid; i < e; i += 256) {
        int g = idx[i];
        int p = atomicAdd(&cur[g], 1);
        outp[p] = i;
    }
}

// ---------------------------------------------------------------------------
// Pool: one CTA (256 thr, 8 warps) per graph; warp-per-row LDG.128 gather,
// 4 independent accumulators.
__device__ __forceinline__ void v4add(float4& a, const float4& v) {
    a.x += v.x; a.y += v.y; a.z += v.z; a.w += v.w;
}

__device__ __forceinline__ void seg_mean_v4(
    const float* __restrict__ data, const int* __restrict__ sorted,
    int s, int e, int tid, int lane, int w,
    int* sidx, float* sred, float* outp) {

    float4 a0 = make_float4(0.f,0.f,0.f,0.f), a1 = a0, a2 = a0, a3 = a0;

    for (int base = s; base < e; base += 256) {
        int m = e - base; if (m > 256) m = 256;
        __syncthreads();
        if (tid < m) sidx[tid] = sorted[base + tid];
        __syncthreads();
        int j = w;
        for (; j + 24 < m; j += 32) {
            float4 v0 = ((const float4*)(data + (long)sidx[j]      * F))[lane];
            float4 v1 = ((const float4*)(data + (long)sidx[j + 8]  * F))[lane];
            float4 v2 = ((const float4*)(data + (long)sidx[j + 16] * F))[lane];
            float4 v3 = ((const float4*)(data + (long)sidx[j + 24] * F))[lane];
            v4add(a0, v0); v4add(a1, v1); v4add(a2, v2); v4add(a3, v3);
        }
        for (; j < m; j += 8) {
            float4 v0 = ((const float4*)(data + (long)sidx[j] * F))[lane];
            v4add(a0, v0);
        }
    }
    v4add(a0, a1); v4add(a2, a3); v4add(a0, a2);

    __syncthreads();
    *(float4*)&sred[w * F + lane * 4] = a0;
    __syncthreads();
    if (tid < F) {
        float sum = 0.f;
#pragma unroll
        for (int ww = 0; ww < 8; ww++) sum += sred[ww * F + tid];
        int c = e - s;
        outp[tid] = sum / (float)(c > 0 ? c : 1);
    }
}

__global__ __launch_bounds__(256) void pool_kernel(
    const float* __restrict__ bonds,
    const float* __restrict__ sites,
    const float* __restrict__ states) {
    __shared__ int   sidx[256];
    __shared__ float sred[8 * F];
    int g = blockIdx.x;
    int tid = threadIdx.x, lane = tid & 31, w = tid >> 5;
    long vb = (long)g * VW;

    seg_mean_v4(bonds, d_bond_sorted, d_off[0][g], d_off[0][g + 1],
                tid, lane, w, sidx, sred, &d_V[vb]);
    seg_mean_v4(sites, d_site_sorted, d_off[1][g], d_off[1][g + 1],
                tid, lane, w, sidx, sred, &d_V[vb + 128]);
    if (tid < F) d_V[vb + 256 + tid] = states[(long)g * F + tid];
}

// ---------------------------------------------------------------------------
// Packed fp32x2 helpers
__device__ __forceinline__ unsigned long long f32x2_dup(float a) {
    unsigned long long r;
    asm("mov.b64 %0, {%1, %1};" : "=l"(r) : "f"(a));
    return r;
}
__device__ __forceinline__ void ffma2(unsigned long long& d,
                                      unsigned long long a,
                                      unsigned long long b) {
    asm("fma.rn.f32x2 %0, %1, %2, %0;" : "+l"(d) : "l"(a), "l"(b));
}
__device__ __forceinline__ float2 f32x2_unpack(unsigned long long v) {
    float lo, hi;
    asm("mov.b64 {%0, %1}, %2;" : "=f"(lo), "=f"(hi) : "l"(v));
    return make_float2(lo, hi);
}

// GEMM: C[M,N] = relu(A[M,K] @ W[N,K]^T + bias). BM=128, BN template,
// BK=16, 256 threads, per-thread 8m x (BN/16)n with f32x2 accumulators.
template <int BN>
__global__ __launch_bounds__(256) void gemm_f32x2(
    const float* __restrict__ A, const float* __restrict__ W,
    const float* __restrict__ bias, float* __restrict__ C,
    int M, int N, int K) {
    constexpr int TN = BN / 16;
    constexpr int P  = TN / 2;
    __shared__ __align__(16) float As[16][132];
    __shared__ __align__(16) float Bs[16][BN + 4];

    int tid = threadIdx.x;
    int tx = tid % 16, ty = tid / 16;
    int m0 = blockIdx.y * 128, n0 = blockIdx.x * BN;
    int lr = tid / 4;
    int lk = (tid % 4) * 4;

    const float* pa0 = &A[(long)(m0 + lr)      * K + lk];
    const float* pa1 = &A[(long)(m0 + lr + 64) * K + lk];
    const float* pw0 = &W[(long)(n0 + (lr % BN))           * K + lk];
    const float* pw1 = (BN > 64) ? &W[(long)(n0 + lr + 64) * K + lk] : pw0;

    float4 ra0 = *(const float4*)pa0;
    float4 ra1 = *(const float4*)pa1;
    float4 rb0 = *(const float4*)pw0;
    float4 rb1 = (BN > 64) ? *(const float4*)pw1 : ra0;

    unsigned long long acc[8][P];
#pragma unroll
    for (int i = 0; i < 8; i++)
#pragma unroll
        for (int j = 0; j < P; j++) acc[i][j] = 0ull;

    for (int k0 = 0; k0 < K; k0 += 16) {
        As[lk + 0][lr] = ra0.x; As[lk + 1][lr] = ra0.y;
        As[lk + 2][lr] = ra0.z; As[lk + 3][lr] = ra0.w;
        As[lk + 0][lr + 64] = ra1.x; As[lk + 1][lr + 64] = ra1.y;
        As[lk + 2][lr + 64] = ra1.z; As[lk + 3][lr + 64] = ra1.w;
        if (BN > 64 || lr < BN) {
            int br = lr % BN;
            Bs[lk + 0][br] = rb0.x; Bs[lk + 1][br] = rb0.y;
            Bs[lk + 2][br] = rb0.z; Bs[lk + 3][br] = rb0.w;
        }
        if (BN > 64) {
            Bs[lk + 0][lr + 64] = rb1.x; Bs[lk + 1][lr + 64] = rb1.y;
            Bs[lk + 2][lr + 64] = rb1.z; Bs[lk + 3][lr + 64] = rb1.w;
        }
        __syncthreads();

        if (k0 + 16 < K) {
            ra0 = *(const float4*)(pa0 + k0 + 16);
            ra1 = *(const float4*)(pa1 + k0 + 16);
            rb0 = *(const float4*)(pw0 + k0 + 16);
            if (BN > 64) rb1 = *(const float4*)(pw1 + k0 + 16);
        }

#pragma unroll
        for (int k = 0; k < 16; k++) {
            float4 av0 = *(const float4*)&As[k][ty * 8];
            float4 av1 = *(const float4*)&As[k][ty * 8 + 4];
            float av[8] = {av0.x, av0.y, av0.z, av0.w,
                           av1.x, av1.y, av1.z, av1.w};
            unsigned long long bb[P];
            {
                ulonglong2 b0 = *(const ulonglong2*)&Bs[k][tx * TN];
                bb[0] = b0.x; bb[1] = b0.y;
                if (P == 4) {
                    ulonglong2 b1 = *(const ulonglong2*)&Bs[k][tx * TN + 4];
                    bb[2] = b1.x; bb[3] = b1.y;
                }
            }
#pragma unroll
            for (int i = 0; i < 8; i++) {
                unsigned long long ai = f32x2_dup(av[i]);
#pragma unroll
                for (int j = 0; j < P; j++) ffma2(acc[i][j], ai, bb[j]);
            }
        }
        __syncthreads();
    }

    float bs[TN];
#pragma unroll
    for (int j = 0; j < TN; j++) bs[j] = bias[n0 + tx * TN + j];

#pragma unroll
    for (int i = 0; i < 8; i++) {
        int m = m0 + ty * 8 + i;
        float o[TN];
#pragma unroll
        for (int j = 0; j < P; j++) {
            float2 v = f32x2_unpack(acc[i][j]);
            float v0 = v.x + bs[2 * j],     v1 = v.y + bs[2 * j + 1];
            o[2 * j]     = v0 > 0.f ? v0 : 0.f;
            o[2 * j + 1] = v1 > 0.f ? v1 : 0.f;
        }
#pragma unroll
        for (int j = 0; j < TN; j += 4)
            *(float4*)&C[(long)m * N + n0 + tx * TN + j] =
                make_float4(o[j], o[j + 1], o[j + 2], o[j + 3]);
    }
}

// ---------------------------------------------------------------------------
extern "C" void kernel_launch(void* const* d_in, const int* in_sizes, int n_in,
                              void* d_out, int out_size) {
    const float* sites  = (const float*)d_in[0];
    const float* bonds  = (const float*)d_in[1];
    const float* states = (const float*)d_in[2];
    const int*   g2s    = (const int*)d_in[3];
    const int*   g2b    = (const int*)d_in[4];
    const float* W1 = (const float*)d_in[5];
    const float* b1 = (const float*)d_in[6];
    const float* W2 = (const float*)d_in[7];
    const float* b2 = (const float*)d_in[8];
    const float* W3 = (const float*)d_in[9];
    const float* b3 = (const float*)d_in[10];
    float* out = (float*)d_out;

    int ns = in_sizes[3];
    int nb = in_sizes[4];

    void *pV, *pH1, *pH2;
    cudaGetSymbolAddress(&pV,  d_V);
    cudaGetSymbolAddress(&pH1, d_H1);
    cudaGetSymbolAddress(&pH2, d_H2);

    hist_priv<<<dim3(NC, 2), 256>>>(g2b, nb, g2s, ns);
    col_scan<<<dim3(G / 256, 2), 256>>>();
    scan_kernel<<<2, 256>>>();
    scatter_priv<<<dim3(NC, 2), 256>>>(g2b, nb, g2s, ns);

    pool_kernel<<<G, 256>>>(bonds, sites, states);

    gemm_f32x2<128><<<dim3(2, G / 128), 256>>>((const float*)pV,  W1, b1, (float*)pH1, G, 256, 384);
    gemm_f32x2<128><<<dim3(2, G / 128), 256>>>((const float*)pH1, W2, b2, (float*)pH2, G, 256, 256);
    gemm_f32x2<64><<<dim3(2, G / 128), 256>>>((const float*)pH2, W3, b3, out,          G, 128, 256);
}